// round 10
// baseline (speedup 1.0000x reference)
#include <cuda_runtime.h>
#include <math.h>
#include <float.h>

#define Bn   4
#define Hn   32
#define HKV  8
#define Gn   4
#define Dn   128
#define Pn   128
#define Sn   64
#define KP   16
#define NEGV (-1000000000.0f)
#define SM_SCALE 0.08838834764831845f

// Scratch (allocation-free rule: __device__ globals)
__device__ float g_scores[Bn*Hn*Pn*Sn];   // 4 MB masked score matrix
__device__ float g_stats [Bn*Hn*Pn];      // per-page max
__device__ float g_part  [Bn*Hn*KP*Dn];   // per-(head,page) partial sum(exp*V)
__device__ float g_pden  [Bn*Hn*KP];      // per-(head,page) partial denom
__device__ int   g_cnt   [Bn*Hn];         // arrival counters (zero-init)

__device__ __forceinline__ void rope_cs(int t, float pos, float& c, float& s) {
    float inv = 1.0f / powf(10000.0f, (float)t * (2.0f / (float)Dn));
    float ang = pos * inv;
    c = cosf(ang); s = sinf(ang);
}

// ---------------------------------------------------------------- kernel 1
// One block per (page, b*HKV): 256 threads, 8 warps x 8 tokens.
// Inline q-RoPE via 64-entry smem cos/sin table (1 rope_cs per tid<64).
// Lane owns dims [4*lane, 4*lane+4). Two 4-token chunks; butterfly
// transpose-reduce of 16 vals over 32 lanes.
__global__ void __launch_bounds__(256, 4)
score_kernel(const float* __restrict__ q,
             const int*   __restrict__ k_cache,
             const float* __restrict__ kv_scale,
             const int*   __restrict__ lengths,
             const int*   __restrict__ timestep)
{
    int p   = blockIdx.x;
    int bh  = blockIdx.y;            // b*HKV + hkv
    int b   = bh >> 3, hkv = bh & 7;
    int tid = threadIdx.x;
    int w   = tid >> 5, lane = tid & 31;
    int len = max(lengths[b], 1);
    int head0 = b*Hn + hkv*Gn;

    if (p*Sn >= len) {
        // fully masked page. Only page Pn-1 can ever be selected while masked.
        if (p == Pn-1 && tid < Sn) {
            #pragma unroll
            for (int g = 0; g < Gn; g++)
                g_scores[(size_t)(head0+g)*Pn*Sn + p*Sn + tid] = NEGV;
        }
        if (tid < Gn) g_stats[(head0+tid)*Pn + p] = NEGV;
        return;
    }

    // cos/sin table: one rope_cs per thread for tid<64
    __shared__ float s_c[64], s_s[64];
    if (tid < 64) {
        float pos = (float)(timestep[0] - 1);
        float c, s; rope_cs(tid, pos, c, s);
        s_c[tid] = c; s_s[tid] = s;
    }
    __syncthreads();

    // q: lane owns dims 4*lane..4*lane+3, all 4 heads; rope inline.
    // dim d<64:  r = q[d]*c[d]   - q[d+64]*s[d]
    // dim d>=64: r = q[d-64]*s[d-64] + q[d]*c[d-64]
    bool low = lane < 16;
    int  d0  = 4*lane;
    int  hb  = low ? d0 : d0 - 64;
    float c4[4], s4[4];
    #pragma unroll
    for (int i = 0; i < 4; i++) { c4[i] = s_c[hb+i]; s4[i] = s_s[hb+i]; }

    float4 qr[Gn];
    #pragma unroll
    for (int g = 0; g < Gn; g++) {
        const float* qh = q + (size_t)(head0+g)*Dn;
        float4 own = *(const float4*)(qh + d0);
        float4 par = *(const float4*)(qh + (low ? d0 + 64 : d0 - 64));
        float o4[4] = {own.x, own.y, own.z, own.w};
        float p4[4] = {par.x, par.y, par.z, par.w};
        float r[4];
        #pragma unroll
        for (int i = 0; i < 4; i++)
            r[i] = low ? (o4[i]*c4[i] - p4[i]*s4[i])
                       : (p4[i]*s4[i] + o4[i]*c4[i]);
        qr[g] = make_float4(r[0], r[1], r[2], r[3]);
    }

    float sks = kv_scale[0] * SM_SCALE;

    const int4* kbase = (const int4*)(k_cache +
        ((((size_t)b*Pn + p)*Sn + w*8)*HKV + hkv)*Dn) + lane;

    // lane -> (g, t) after butterfly: g = (lane>>3)&3, t = (lane>>1)&3
    int g  = (lane >> 3) & 3;
    int tt = (lane >> 1) & 3;

    float pmax = NEGV;
    #pragma unroll
    for (int c = 0; c < 2; c++) {
        int4 kv[4];
        #pragma unroll
        for (int t = 0; t < 4; t++)
            kv[t] = kbase[(size_t)(c*4 + t) * (HKV*Dn/4)];

        float vals[16];
        #pragma unroll
        for (int i = 0; i < 16; i++) vals[i] = 0.f;

        #pragma unroll
        for (int t = 0; t < 4; t++) {
            float f0=(float)kv[t].x, f1=(float)kv[t].y,
                  f2=(float)kv[t].z, f3=(float)kv[t].w;
            #pragma unroll
            for (int gg = 0; gg < Gn; gg++)
                vals[gg*4+t] += f0*qr[gg].x + f1*qr[gg].y
                              + f2*qr[gg].z + f3*qr[gg].w;
        }

        // butterfly: stages (o=16,d=8) (8,4) (4,2) (2,1); then fold lane bit 0
        #pragma unroll
        for (int st = 0; st < 4; st++) {
            int o = 16 >> st, d = 8 >> st;
            #pragma unroll
            for (int a = 0; a < 8; a++) {
                if (a >= d) break;
                float lo = vals[a], hi = vals[a+d];
                float send = (lane & o) ? lo : hi;
                float recv = __shfl_xor_sync(0xffffffffu, send, o);
                vals[a] = ((lane & o) ? hi : lo) + recv;
            }
        }
        float v = vals[0] + __shfl_xor_sync(0xffffffffu, vals[0], 1);

        int tok = w*8 + c*4 + tt;
        bool valid = p*Sn + tok < len;
        float sc = valid ? v*sks : NEGV;
        if (!(lane & 1))
            g_scores[(size_t)(head0+g)*Pn*Sn + p*Sn + tok] = sc;
        pmax = fmaxf(pmax, sc);
    }

    // per-g page max: reduce over lane bits 4,2 (bit 1 already duplicated)
    pmax = fmaxf(pmax, __shfl_xor_sync(0xffffffffu, pmax, 4));
    pmax = fmaxf(pmax, __shfl_xor_sync(0xffffffffu, pmax, 2));

    __shared__ float smax[8][Gn];
    if ((lane & 7) == 0) smax[w][g] = pmax;
    __syncthreads();
    if (tid < 32) {
        // tid = g2*8 + w2
        float v = smax[tid & 7][tid >> 3];
        #pragma unroll
        for (int o = 4; o >= 1; o >>= 1)
            v = fmaxf(v, __shfl_xor_sync(0xffffffffu, v, o));
        if ((tid & 7) == 0)
            g_stats[(head0 + (tid >> 3))*Pn + p] = v;
    }
}

// ---------------------------------------------------------------- kernel 2
// One block per (head, kp): 2048 blocks x 128 threads.
// Warp 0 re-derives the kp-th top page (jax.lax.top_k semantics), the
// current-token score (raw q.k — RoPE at equal positions preserves dots)
// and the softmax max; then exp-weighted V partial sum. Last-arriving block
// per head finalizes (deterministic fixed-order sum).
__device__ __forceinline__ unsigned int fkey(float f) {
    unsigned int u = __float_as_uint(f);
    return u ^ ((u & 0x80000000u) ? 0xFFFFFFFFu : 0x80000000u);
}

__global__ void attn_kernel(const float* __restrict__ q,
                            const float* __restrict__ k_cur,
                            const int*   __restrict__ v_cache,
                            const float* __restrict__ v_cur,
                            const float* __restrict__ kv_scale,
                            float* __restrict__ out,
                            float* __restrict__ out_idx, int write_idx)
{
    __shared__ float  w[Sn];
    __shared__ float4 part[4][32];
    __shared__ float  s_m, s_cur;
    __shared__ int    s_page, s_last;

    int bid  = blockIdx.x;
    int head = bid >> 4;
    int kp   = bid & (KP-1);
    int tid  = threadIdx.x;
    int warp = tid >> 5, lane = tid & 31;
    int b = head >> 5;                 // head / Hn
    int hkv = (head & (Hn-1)) >> 2;    // (head % Hn) / Gn

    const float* st = g_stats + head*Pn;

    if (warp == 0) {
        // current-token score: rope(q).rope(k) == q.k (same-position rotation)
        float4 qa = *(const float4*)(q + (size_t)head*Dn + 4*lane);
        float4 ka = *(const float4*)(k_cur + (size_t)(b*HKV + hkv)*Dn + 4*lane);
        float prod = qa.x*ka.x + qa.y*ka.y + qa.z*ka.z + qa.w*ka.w;
        #pragma unroll
        for (int o = 16; o >= 1; o >>= 1)
            prod += __shfl_xor_sync(0xffffffffu, prod, o);
        float curv = prod * SM_SCALE;

        // top-k: iterate to rank kp (or rank 0 only, for forced page 127)
        unsigned long long keys[4];
        #pragma unroll
        for (int j = 0; j < 4; j++) {
            int idx = lane + j*32;
            keys[j] = (idx < Pn-1)
                ? (((unsigned long long)fkey(st[idx]) << 32) | (unsigned int)(~idx))
                : 0ull;
        }

        int iters = (kp == KP-1) ? 1 : (kp + 1);
        int bidx = 0, bidx0 = 0;
        for (int it = 0; it < iters; it++) {
            unsigned long long best = keys[0];
            #pragma unroll
            for (int j = 1; j < 4; j++) best = (keys[j] > best) ? keys[j] : best;
            #pragma unroll
            for (int o = 16; o >= 1; o >>= 1) {
                unsigned long long u = __shfl_xor_sync(0xffffffffu, best, o);
                best = (u > best) ? u : best;
            }
            bidx = (int)(~(unsigned int)(best & 0xFFFFFFFFull));
            if (it == 0) bidx0 = bidx;
            #pragma unroll
            for (int j = 0; j < 4; j++) if (keys[j] == best) keys[j] = 0ull;
        }
        int page = (kp == KP-1) ? (Pn-1) : bidx;
        float m = fmaxf(fmaxf(st[bidx0], st[Pn-1]), curv);

        if (lane == 0) {
            s_page = page; s_m = m; s_cur = curv;
            if (write_idx) out_idx[head*KP + kp] = (float)page;
        }
    }
    __syncthreads();

    int page = s_page;
    float m  = s_m;

    if (tid < Sn)
        w[tid] = expf(g_scores[(size_t)head*Pn*Sn + page*Sn + tid] - m);
    __syncthreads();

    // partial denom (warp 0)
    if (warp == 0) {
        float s = w[lane] + w[lane + 32];
        #pragma unroll
        for (int o = 16; o >= 1; o >>= 1)
            s += __shfl_xor_sync(0xffffffffu, s, o);
        if (lane == 0) g_pden[head*KP + kp] = s;
    }

    // V accumulation: warp g handles tokens s == g (mod 4); lane -> 4 dims
    const int4* vp = (const int4*)(v_cache +
        (((size_t)(b*Pn + page)*Sn)*HKV + hkv)*Dn) + lane;
    float a0=0.f, a1=0.f, a2=0.f, a3=0.f;
    #pragma unroll
    for (int s2 = 0; s2 < Sn/4; s2++) {
        int srow = s2*4 + warp;
        int4 vv = vp[(size_t)srow * (HKV*Dn/4)];
        float ww = w[srow];
        a0 += ww*(float)vv.x; a1 += ww*(float)vv.y;
        a2 += ww*(float)vv.z; a3 += ww*(float)vv.w;
    }
    part[warp][lane] = make_float4(a0, a1, a2, a3);
    __syncthreads();

    {
        int lane2 = tid >> 2, comp = tid & 3;
        float acc = 0.f;
        #pragma unroll
        for (int g2 = 0; g2 < 4; g2++) {
            float4 pv = part[g2][lane2];
            acc += (comp==0) ? pv.x : (comp==1) ? pv.y : (comp==2) ? pv.z : pv.w;
        }
        g_part[((size_t)head*KP + kp)*Dn + tid] = acc;
    }

    // arrival counter: last block of this head finalizes (deterministic sum)
    __threadfence();
    __syncthreads();
    if (tid == 0) {
        int old = atomicAdd(&g_cnt[head], 1);
        s_last = (old == KP-1) ? 1 : 0;
        if (s_last) g_cnt[head] = 0;   // reset for next graph replay
    }
    __syncthreads();
    if (!s_last) return;
    __threadfence();

    float acc = 0.f;
    const float* pp = g_part + (size_t)head*KP*Dn + tid;
    #pragma unroll
    for (int j = 0; j < KP; j++) acc += pp[j*Dn];

    float ecur = expf(s_cur - m);
    float den = ecur;
    const float* dp = g_pden + head*KP;
    #pragma unroll
    for (int j = 0; j < KP; j++) den += dp[j];

    float o = acc * kv_scale[1] + ecur * v_cur[(size_t)(b*HKV + hkv)*Dn + tid];
    out[(size_t)head*Dn + tid] = o / den;
}

// ---------------------------------------------------------------- launch
extern "C" void kernel_launch(void* const* d_in, const int* in_sizes, int n_in,
                              void* d_out, int out_size)
{
    const float* q        = (const float*)d_in[0];
    const float* k        = (const float*)d_in[1];
    const float* v        = (const float*)d_in[2];
    const float* kv_scale = (const float*)d_in[3];
    const int*   k_cache  = (const int*)  d_in[4];
    const int*   v_cache  = (const int*)  d_in[5];
    const int*   lengths  = (const int*)  d_in[6];
    const int*   timestep = (const int*)  d_in[7];
    float* out = (float*)d_out;

    int write_idx = (out_size >= Bn*Hn*Dn + Bn*Hn*KP) ? 1 : 0;

    score_kernel<<<dim3(Pn, Bn*HKV), 256>>>(q, k_cache, kv_scale, lengths, timestep);
    attn_kernel<<<Bn*Hn*KP, 128>>>(q, k, v_cache, v, kv_scale, out,
                                   out + Bn*Hn*Dn, write_idx);
}

// round 11
// speedup vs baseline: 1.0377x; 1.0377x over previous
#include <cuda_runtime.h>
#include <math.h>
#include <float.h>

#define Bn   4
#define Hn   32
#define HKV  8
#define Gn   4
#define Dn   128
#define Pn   128
#define Sn   64
#define KP   16
#define NEGV (-1000000000.0f)
#define SM_SCALE 0.08838834764831845f

// Scratch (allocation-free rule: __device__ globals)
__device__ float g_scores[Bn*Hn*Pn*Sn];   // 4 MB masked score matrix
__device__ float g_stats [Bn*Hn*Pn];      // per-page max
__device__ float g_part  [Bn*Hn*KP*Dn];   // per-(head,page) partial sum(exp*V)
__device__ float g_pden  [Bn*Hn*KP];      // per-(head,page) partial denom
__device__ int   g_cnt   [Bn*Hn];         // arrival counters (zero-init)

__device__ __forceinline__ void rope_cs(int t, float pos, float& c, float& s) {
    float inv = 1.0f / powf(10000.0f, (float)t * (2.0f / (float)Dn));
    float ang = pos * inv;
    c = cosf(ang); s = sinf(ang);
}

// ---------------------------------------------------------------- kernel 1
// One block per (page, b*HKV): 256 threads, 8 warps x 8 tokens.
// Chunk-0 K loads issued before q-RoPE setup (latency overlap).
// Inline q-RoPE via 64-entry smem cos/sin table. Lane owns dims
// [4*lane,4*lane+4); butterfly transpose-reduce of 16 vals over 32 lanes.
__global__ void __launch_bounds__(256, 4)
score_kernel(const float* __restrict__ q,
             const int*   __restrict__ k_cache,
             const float* __restrict__ kv_scale,
             const int*   __restrict__ lengths,
             const int*   __restrict__ timestep)
{
    int p   = blockIdx.x;
    int bh  = blockIdx.y;            // b*HKV + hkv
    int b   = bh >> 3, hkv = bh & 7;
    int tid = threadIdx.x;
    int w   = tid >> 5, lane = tid & 31;
    int len = max(lengths[b], 1);
    int head0 = b*Hn + hkv*Gn;

    if (p*Sn >= len) {
        // fully masked page. Only page Pn-1 can ever be selected while masked.
        if (p == Pn-1 && tid < Sn) {
            #pragma unroll
            for (int g = 0; g < Gn; g++)
                g_scores[(size_t)(head0+g)*Pn*Sn + p*Sn + tid] = NEGV;
        }
        if (tid < Gn) g_stats[(head0+tid)*Pn + p] = NEGV;
        return;
    }

    __shared__ float s_c[64], s_s[64];
    if (tid < 64) {
        float pos = (float)(timestep[0] - 1);
        float c, s; rope_cs(tid, pos, c, s);
        s_c[tid] = c; s_s[tid] = s;
    }

    const int4* kbase = (const int4*)(k_cache +
        ((((size_t)b*Pn + p)*Sn + w*8)*HKV + hkv)*Dn) + lane;

    // issue chunk-0 K loads before q setup (overlap LDG latency)
    int4 kv0[4];
    #pragma unroll
    for (int t = 0; t < 4; t++)
        kv0[t] = kbase[(size_t)t * (HKV*Dn/4)];

    __syncthreads();

    // q: lane owns dims 4*lane..4*lane+3, all 4 heads; rope inline.
    bool low = lane < 16;
    int  d0  = 4*lane;
    int  hb  = low ? d0 : d0 - 64;
    float c4[4], s4[4];
    #pragma unroll
    for (int i = 0; i < 4; i++) { c4[i] = s_c[hb+i]; s4[i] = s_s[hb+i]; }

    float4 qr[Gn];
    #pragma unroll
    for (int g = 0; g < Gn; g++) {
        const float* qh = q + (size_t)(head0+g)*Dn;
        float4 own = *(const float4*)(qh + d0);
        float4 par = *(const float4*)(qh + (low ? d0 + 64 : d0 - 64));
        float o4[4] = {own.x, own.y, own.z, own.w};
        float p4[4] = {par.x, par.y, par.z, par.w};
        float r[4];
        #pragma unroll
        for (int i = 0; i < 4; i++)
            r[i] = low ? (o4[i]*c4[i] - p4[i]*s4[i])
                       : (p4[i]*s4[i] + o4[i]*c4[i]);
        qr[g] = make_float4(r[0], r[1], r[2], r[3]);
    }

    float sks = kv_scale[0] * SM_SCALE;

    // lane -> (g, t) after butterfly: g = (lane>>3)&3, t = (lane>>1)&3
    int g  = (lane >> 3) & 3;
    int tt = (lane >> 1) & 3;

    float pmax = NEGV;
    #pragma unroll
    for (int c = 0; c < 2; c++) {
        int4 kv[4];
        if (c == 0) {
            #pragma unroll
            for (int t = 0; t < 4; t++) kv[t] = kv0[t];
        } else {
            #pragma unroll
            for (int t = 0; t < 4; t++)
                kv[t] = kbase[(size_t)(4 + t) * (HKV*Dn/4)];
        }

        float vals[16];
        #pragma unroll
        for (int i = 0; i < 16; i++) vals[i] = 0.f;

        #pragma unroll
        for (int t = 0; t < 4; t++) {
            float f0=(float)kv[t].x, f1=(float)kv[t].y,
                  f2=(float)kv[t].z, f3=(float)kv[t].w;
            #pragma unroll
            for (int gg = 0; gg < Gn; gg++)
                vals[gg*4+t] += f0*qr[gg].x + f1*qr[gg].y
                              + f2*qr[gg].z + f3*qr[gg].w;
        }

        // butterfly: stages (o=16,d=8) (8,4) (4,2) (2,1); then fold lane bit 0
        #pragma unroll
        for (int st = 0; st < 4; st++) {
            int o = 16 >> st, d = 8 >> st;
            #pragma unroll
            for (int a = 0; a < 8; a++) {
                if (a >= d) break;
                float lo = vals[a], hi = vals[a+d];
                float send = (lane & o) ? lo : hi;
                float recv = __shfl_xor_sync(0xffffffffu, send, o);
                vals[a] = ((lane & o) ? hi : lo) + recv;
            }
        }
        float v = vals[0] + __shfl_xor_sync(0xffffffffu, vals[0], 1);

        int tok = w*8 + c*4 + tt;
        bool valid = p*Sn + tok < len;
        float sc = valid ? v*sks : NEGV;
        if (!(lane & 1))
            g_scores[(size_t)(head0+g)*Pn*Sn + p*Sn + tok] = sc;
        pmax = fmaxf(pmax, sc);
    }

    // per-g page max: reduce over lane bits 4,2 (bit 1 already duplicated)
    pmax = fmaxf(pmax, __shfl_xor_sync(0xffffffffu, pmax, 4));
    pmax = fmaxf(pmax, __shfl_xor_sync(0xffffffffu, pmax, 2));

    __shared__ float smax[8][Gn];
    if ((lane & 7) == 0) smax[w][g] = pmax;
    __syncthreads();
    if (tid < 32) {
        // tid = g2*8 + w2
        float v = smax[tid & 7][tid >> 3];
        #pragma unroll
        for (int o = 4; o >= 1; o >>= 1)
            v = fmaxf(v, __shfl_xor_sync(0xffffffffu, v, o));
        if ((tid & 7) == 0)
            g_stats[(head0 + (tid >> 3))*Pn + p] = v;
    }
}

// ---------------------------------------------------------------- kernel 2
// One block per (head, kp): 2048 blocks x 128 threads.
// EVERY warp independently derives the kp-th top page (REDUX argmax,
// jax.lax.top_k semantics incl. min-index tie-break), current score and
// softmax max -> no inter-warp sync before V loads. Weights live in lane
// registers, broadcast by shfl. Last-arriving block per head finalizes.
__device__ __forceinline__ unsigned int fkey(float f) {
    unsigned int u = __float_as_uint(f);
    return u ^ ((u & 0x80000000u) ? 0xFFFFFFFFu : 0x80000000u);
}

__global__ void attn_kernel(const float* __restrict__ q,
                            const float* __restrict__ k_cur,
                            const int*   __restrict__ v_cache,
                            const float* __restrict__ v_cur,
                            const float* __restrict__ kv_scale,
                            float* __restrict__ out,
                            float* __restrict__ out_idx, int write_idx)
{
    __shared__ float4 part[4][32];
    __shared__ float  wden[4];
    __shared__ int    s_last;

    int bid  = blockIdx.x;
    int head = bid >> 4;
    int kp   = bid & (KP-1);
    int tid  = threadIdx.x;
    int warp = tid >> 5, lane = tid & 31;
    int b = head >> 5;                 // head / Hn
    int hkv = (head & (Hn-1)) >> 2;    // (head % Hn) / Gn

    const float* st = g_stats + head*Pn;

    // ---- per-warp: topk keys (32-bit monotone floats; 0 = dead/invalid)
    unsigned int f[4];
    #pragma unroll
    for (int j = 0; j < 4; j++) {
        int idx = lane + j*32;
        f[j] = (idx < Pn-1) ? fkey(st[idx]) : 0u;
    }

    // current-token score: rope(q).rope(k) == q.k (same-position rotation)
    float4 qa = *(const float4*)(q + (size_t)head*Dn + 4*lane);
    float4 ka = *(const float4*)(k_cur + (size_t)(b*HKV + hkv)*Dn + 4*lane);
    float prod = qa.x*ka.x + qa.y*ka.y + qa.z*ka.z + qa.w*ka.w;
    #pragma unroll
    for (int o = 16; o >= 1; o >>= 1)
        prod += __shfl_xor_sync(0xffffffffu, prod, o);
    float curv = prod * SM_SCALE;

    // iterate to rank kp (rank 0 only for the forced page Pn-1)
    int iters = (kp == KP-1) ? 1 : (kp + 1);
    unsigned int sel = 0, sel0 = 0;
    for (int it = 0; it < iters; it++) {
        unsigned int local = max(max(f[0], f[1]), max(f[2], f[3]));
        unsigned int best  = __reduce_max_sync(0xffffffffu, local);
        unsigned int my = 0xFFFFFFFFu;
        #pragma unroll
        for (int j = 0; j < 4; j++)
            if (f[j] == best) my = min(my, (unsigned int)(lane + j*32));
        sel = __reduce_min_sync(0xffffffffu, my);
        if (it == 0) sel0 = sel;
        #pragma unroll
        for (int j = 0; j < 4; j++)
            if ((unsigned int)(lane + j*32) == sel) f[j] = 0u;
    }
    int page = (kp == KP-1) ? (Pn-1) : (int)sel;
    float m = fmaxf(fmaxf(st[sel0], st[Pn-1]), curv);

    if (tid == 0 && write_idx) out_idx[head*KP + kp] = (float)page;

    // ---- weights in registers: lane s2 (<16) owns token 4*s2 + warp
    float wv = 0.f;
    if (lane < 16)
        wv = __expf(g_scores[(size_t)head*Pn*Sn + page*Sn + 4*lane + warp] - m);

    // per-warp denom partial
    {
        float d = wv;
        #pragma unroll
        for (int o = 16; o >= 1; o >>= 1)
            d += __shfl_xor_sync(0xffffffffu, d, o);
        if (lane == 0) wden[warp] = d;
    }

    // ---- V accumulation: warp handles tokens s == warp (mod 4)
    const int4* vp = (const int4*)(v_cache +
        (((size_t)(b*Pn + page)*Sn)*HKV + hkv)*Dn) + lane;
    float a0=0.f, a1=0.f, a2=0.f, a3=0.f;
    #pragma unroll
    for (int s2 = 0; s2 < 16; s2++) {
        int4 vv = vp[(size_t)(s2*4 + warp) * (HKV*Dn/4)];
        float ww = __shfl_sync(0xffffffffu, wv, s2);
        a0 += ww*(float)vv.x; a1 += ww*(float)vv.y;
        a2 += ww*(float)vv.z; a3 += ww*(float)vv.w;
    }
    part[warp][lane] = make_float4(a0, a1, a2, a3);
    __syncthreads();

    {
        int lane2 = tid >> 2, comp = tid & 3;
        float acc = 0.f;
        #pragma unroll
        for (int g2 = 0; g2 < 4; g2++) {
            float4 pv = part[g2][lane2];
            acc += (comp==0) ? pv.x : (comp==1) ? pv.y : (comp==2) ? pv.z : pv.w;
        }
        g_part[((size_t)head*KP + kp)*Dn + tid] = acc;
    }
    if (tid == 0)
        g_pden[head*KP + kp] = (wden[0] + wden[1]) + (wden[2] + wden[3]);

    // arrival counter: last block of this head finalizes (deterministic sum)
    __threadfence();
    __syncthreads();
    if (tid == 0) {
        int old = atomicAdd(&g_cnt[head], 1);
        s_last = (old == KP-1) ? 1 : 0;
        if (s_last) g_cnt[head] = 0;   // reset for next graph replay
    }
    __syncthreads();
    if (!s_last) return;
    __threadfence();

    float acc = 0.f;
    const float* pp = g_part + (size_t)head*KP*Dn + tid;
    #pragma unroll
    for (int j = 0; j < KP; j++) acc += pp[j*Dn];

    float ecur = __expf(curv - m);
    float den = ecur;
    const float* dp = g_pden + head*KP;
    #pragma unroll
    for (int j = 0; j < KP; j++) den += dp[j];

    float o = acc * kv_scale[1] + ecur * v_cur[(size_t)(b*HKV + hkv)*Dn + tid];
    out[(size_t)head*Dn + tid] = o / den;
}

// ---------------------------------------------------------------- launch
extern "C" void kernel_launch(void* const* d_in, const int* in_sizes, int n_in,
                              void* d_out, int out_size)
{
    const float* q        = (const float*)d_in[0];
    const float* k        = (const float*)d_in[1];
    const float* v        = (const float*)d_in[2];
    const float* kv_scale = (const float*)d_in[3];
    const int*   k_cache  = (const int*)  d_in[4];
    const int*   v_cache  = (const int*)  d_in[5];
    const int*   lengths  = (const int*)  d_in[6];
    const int*   timestep = (const int*)  d_in[7];
    float* out = (float*)d_out;

    int write_idx = (out_size >= Bn*Hn*Dn + Bn*Hn*KP) ? 1 : 0;

    score_kernel<<<dim3(Pn, Bn*HKV), 256>>>(q, k_cache, kv_scale, lengths, timestep);
    attn_kernel<<<Bn*Hn*KP, 128>>>(q, k, v_cache, v, kv_scale, out,
                                   out + Bn*Hn*Dn, write_idx);
}